// round 16
// baseline (speedup 1.0000x reference)
#include <cuda_runtime.h>
#include <cuda_bf16.h>
#include <cstdint>

#define B_DIM 4
#define T_DIM 256
#define S_DIM 256
#define D_DIM 512

// ---------------- fp32 scratch ----------------
__device__ float g_wq[B_DIM * T_DIM * D_DIM];        // 2 MB
__device__ float g_uh[B_DIM * S_DIM * D_DIM];        // 2 MB
__device__ float g_score4[4][B_DIM * T_DIM * S_DIM]; // 4 MB (four d-quarters)
__device__ float g_out2[B_DIM * T_DIM * D_DIM];      // 2 MB (output @ Wout[512:])

// ---------------- bf16 split scratch ----------------
__device__ __nv_bfloat16 g_out_hi[524288],  g_out_lo[524288];    // output [1024,512]
__device__ __nv_bfloat16 g_ctx_hi[524288],  g_ctx_lo[524288];    // context [1024,512]
__device__ __nv_bfloat16 g_ctxT_hi[524288], g_ctxT_lo[524288];   // context^T [4][512][256]
__device__ __nv_bfloat16 g_WqT_hi[262144],  g_WqT_lo[262144];    // Wq^T [512,512]
__device__ __nv_bfloat16 g_WcT_hi[262144],  g_WcT_lo[262144];    // Wc^T [512,512]
__device__ __nv_bfloat16 g_WoT_hi[524288],  g_WoT_lo[524288];    // Wout^T [512 rows][1024 k]
__device__ __nv_bfloat16 g_at_hi[262144],   g_at_lo[262144];     // attn [1024,256]
__device__ __nv_bfloat16 g_mx_hi[524288],   g_mx_lo[524288];     // mix [1024,512]

// ---------------- streams/events for graph fork-join (created before main) ----------
static cudaStream_t s1;
static cudaEvent_t  evFork, ev1, ev2;
struct StreamInit {
    StreamInit() {
        cudaStreamCreateWithFlags(&s1, cudaStreamNonBlocking);
        cudaEventCreateWithFlags(&evFork, cudaEventDisableTiming);
        cudaEventCreateWithFlags(&ev1, cudaEventDisableTiming);
        cudaEventCreateWithFlags(&ev2, cudaEventDisableTiming);
    }
};
static StreamInit g_streams_init;

__device__ __forceinline__ float tanh_fast(float x) {
    float y;
    asm("tanh.approx.f32 %0, %1;" : "=f"(y) : "f"(x));
    return y;
}

// ---------------- fused staging: all splits + transposes in ONE launch ------------
__device__ __forceinline__ void do_split_block(
    const float* __restrict__ src,
    __nv_bfloat16* __restrict__ hi, __nv_bfloat16* __restrict__ lo, int blk)
{
    int i = blk * 1024 + threadIdx.x * 4;
    float4 x = *(const float4*)(src + i);
    __nv_bfloat16 h0 = __float2bfloat16(x.x);
    __nv_bfloat16 h1 = __float2bfloat16(x.y);
    __nv_bfloat16 h2 = __float2bfloat16(x.z);
    __nv_bfloat16 h3 = __float2bfloat16(x.w);
    __nv_bfloat162 hh0; hh0.x = h0; hh0.y = h1;
    __nv_bfloat162 hh1; hh1.x = h2; hh1.y = h3;
    __nv_bfloat162 ll0;
    ll0.x = __float2bfloat16(x.x - __bfloat162float(h0));
    ll0.y = __float2bfloat16(x.y - __bfloat162float(h1));
    __nv_bfloat162 ll1;
    ll1.x = __float2bfloat16(x.z - __bfloat162float(h2));
    ll1.y = __float2bfloat16(x.w - __bfloat162float(h3));
    *(__nv_bfloat162*)(hi + i)     = hh0;
    *(__nv_bfloat162*)(hi + i + 2) = hh1;
    *(__nv_bfloat162*)(lo + i)     = ll0;
    *(__nv_bfloat162*)(lo + i + 2) = ll1;
}

__device__ __forceinline__ void do_splitT_block(
    float (*tile)[33],
    const float* __restrict__ src,
    __nv_bfloat16* __restrict__ hiT, __nv_bfloat16* __restrict__ loT,
    int R, int C, int bx, int by)
{
    const int r0 = by * 32, c0 = bx * 32;
    const int tx = threadIdx.x & 31, ty = threadIdx.x >> 5;   // 32 x 8

    #pragma unroll
    for (int i = 0; i < 4; i++)
        tile[ty + i * 8][tx] = src[(long)(r0 + ty + i * 8) * C + c0 + tx];
    __syncthreads();
    #pragma unroll
    for (int i = 0; i < 4; i++) {
        int cr = c0 + ty + i * 8;
        float x = tile[tx][ty + i * 8];
        __nv_bfloat16 h = __float2bfloat16(x);
        hiT[(long)cr * R + r0 + tx] = h;
        loT[(long)cr * R + r0 + tx] = __float2bfloat16(x - __bfloat162float(h));
    }
}

__global__ __launch_bounds__(256) void stage_all(
    const float* __restrict__ output, const float* __restrict__ context,
    const float* __restrict__ Wq, const float* __restrict__ Wc,
    const float* __restrict__ Wout)
{
    __shared__ float tile[32][33];
    const int j = blockIdx.x;
    if (j < 512) {
        do_split_block(output, g_out_hi, g_out_lo, j);
    } else if (j < 1024) {
        do_split_block(context, g_ctx_hi, g_ctx_lo, j - 512);
    } else if (j < 1280) {
        int k = j - 1024;
        do_splitT_block(tile, Wq, g_WqT_hi, g_WqT_lo, 512, 512, k & 15, k >> 4);
    } else if (j < 1536) {
        int k = j - 1280;
        do_splitT_block(tile, Wc, g_WcT_hi, g_WcT_lo, 512, 512, k & 15, k >> 4);
    } else if (j < 2048) {
        int k = j - 1536;
        do_splitT_block(tile, Wout, g_WoT_hi, g_WoT_lo, 1024, 512, k & 15, k >> 4);
    } else {
        int k = j - 2048;
        int z = k >> 7, rem = k & 127;
        const long s = (long)S_DIM * D_DIM;
        do_splitT_block(tile, context + z * s, g_ctxT_hi + z * s, g_ctxT_lo + z * s,
                        256, 512, rem & 15, rem >> 4);
    }
}

// ---------------- split-bf16 tensor-core GEMM (256 thr, 8 warps, 64x64 tile) ----
// C = A @ B^T (+bias) (+Cacc). BT rows have stride BTstride (>= Ktot slice).
#define MMA_BF16(d, a, b)                                                     \
    asm volatile("mma.sync.aligned.m16n8k16.row.col.f32.bf16.bf16.f32 "       \
                 "{%0,%1,%2,%3},{%4,%5,%6,%7},{%8,%9},{%0,%1,%2,%3};"         \
                 : "+f"((d)[0]), "+f"((d)[1]), "+f"((d)[2]), "+f"((d)[3])     \
                 : "r"((a)[0]), "r"((a)[1]), "r"((a)[2]), "r"((a)[3]),        \
                   "r"((b)[0]), "r"((b)[1]))

__global__ __launch_bounds__(256) void gemm_bf16s(
    const __nv_bfloat16* __restrict__ Ahi, const __nv_bfloat16* __restrict__ Alo,
    const __nv_bfloat16* __restrict__ BThi, const __nv_bfloat16* __restrict__ BTlo,
    int BTstride,
    float* __restrict__ C,
    __nv_bfloat16* __restrict__ Chi, __nv_bfloat16* __restrict__ Clo,
    const float* __restrict__ Cacc,
    int N, int Ktot, const float* __restrict__ bias,
    long sA, long sB, long sC)
{
    Ahi  += (long)blockIdx.z * sA;  Alo  += (long)blockIdx.z * sA;
    BThi += (long)blockIdx.z * sB;  BTlo += (long)blockIdx.z * sB;
    if (C)   C   += (long)blockIdx.z * sC;
    if (Chi) { Chi += (long)blockIdx.z * sC; Clo += (long)blockIdx.z * sC; }

    __shared__ __align__(16) __nv_bfloat16 As[2][2][64 * 24];
    __shared__ __align__(16) __nv_bfloat16 Bs[2][2][64 * 24];

    const int tid  = threadIdx.x;
    const int lane = tid & 31;
    const int wid  = tid >> 5;
    const int wm   = wid & 1;
    const int wn   = wid >> 1;
    const int m0   = blockIdx.y * 64;
    const int n0   = blockIdx.x * 64;
    const int g    = lane >> 2;
    const int t    = lane & 3;
    const int arow = tid >> 2;
    const int part = (tid >> 1) & 1;
    const int seg  = tid & 1;

    const int KT = Ktot >> 4;

    int4 ra, rb;

#define LDG(kt) {                                                              \
        int gk = (kt) << 4;                                                    \
        long aoff = (long)(m0 + arow) * Ktot + gk + seg * 8;                   \
        ra = *(const int4*)((part ? Alo : Ahi) + aoff);                        \
        long boff = (long)(n0 + arow) * BTstride + gk + seg * 8;               \
        rb = *(const int4*)((part ? BTlo : BThi) + boff);                      \
    }

#define STS(bf) {                                                              \
        int so = arow * 24 + seg * 8;                                          \
        *(int4*)&As[bf][part][so] = ra;                                        \
        *(int4*)&Bs[bf][part][so] = rb;                                        \
    }

    float acc[2][2][4] = {};

    LDG(0); STS(0);
    __syncthreads();

    for (int kt = 0; kt < KT; kt++) {
        const int buf = kt & 1;
        if (kt + 1 < KT) LDG(kt + 1);

        uint32_t ah[2][4], al[2][4], bh[2][2], bl[2][2];
        const __nv_bfloat16* pah = &As[buf][0][0];
        const __nv_bfloat16* pal = &As[buf][1][0];
        const __nv_bfloat16* pbh = &Bs[buf][0][0];
        const __nv_bfloat16* pbl = &Bs[buf][1][0];

        #pragma unroll
        for (int mi = 0; mi < 2; mi++) {
            int base = (wm * 32 + mi * 16 + g) * 24 + 2 * t;
            ah[mi][0] = *(const uint32_t*)(pah + base);
            ah[mi][1] = *(const uint32_t*)(pah + base + 8 * 24);
            ah[mi][2] = *(const uint32_t*)(pah + base + 8);
            ah[mi][3] = *(const uint32_t*)(pah + base + 8 * 24 + 8);
            al[mi][0] = *(const uint32_t*)(pal + base);
            al[mi][1] = *(const uint32_t*)(pal + base + 8 * 24);
            al[mi][2] = *(const uint32_t*)(pal + base + 8);
            al[mi][3] = *(const uint32_t*)(pal + base + 8 * 24 + 8);
        }
        #pragma unroll
        for (int nj = 0; nj < 2; nj++) {
            int base = (wn * 16 + nj * 8 + g) * 24 + 2 * t;
            bh[nj][0] = *(const uint32_t*)(pbh + base);
            bh[nj][1] = *(const uint32_t*)(pbh + base + 8);
            bl[nj][0] = *(const uint32_t*)(pbl + base);
            bl[nj][1] = *(const uint32_t*)(pbl + base + 8);
        }

        #pragma unroll
        for (int mi = 0; mi < 2; mi++)
            #pragma unroll
            for (int nj = 0; nj < 2; nj++) {
                MMA_BF16(acc[mi][nj], ah[mi], bh[nj]);
                MMA_BF16(acc[mi][nj], ah[mi], bl[nj]);
                MMA_BF16(acc[mi][nj], al[mi], bh[nj]);
            }

        if (kt + 1 < KT) STS(buf ^ 1);
        __syncthreads();
    }

    #pragma unroll
    for (int mi = 0; mi < 2; mi++)
        #pragma unroll
        for (int nj = 0; nj < 2; nj++) {
            int r = m0 + wm * 32 + mi * 16 + g;
            int c = n0 + wn * 16 + nj * 8 + 2 * t;
            float b0 = 0.f, b1 = 0.f;
            if (bias) { b0 = bias[c]; b1 = bias[c + 1]; }
            float v0 = acc[mi][nj][0] + b0, v1 = acc[mi][nj][1] + b1;
            float v2 = acc[mi][nj][2] + b0, v3 = acc[mi][nj][3] + b1;
            if (Cacc) {
                float2 a0 = *(const float2*)&Cacc[(long)r * N + c];
                float2 a1 = *(const float2*)&Cacc[(long)(r + 8) * N + c];
                v0 += a0.x; v1 += a0.y; v2 += a1.x; v3 += a1.y;
            }
            if (Chi) {
                __nv_bfloat162 hh0, ll0, hh1, ll1;
                hh0.x = __float2bfloat16(v0); hh0.y = __float2bfloat16(v1);
                ll0.x = __float2bfloat16(v0 - __bfloat162float(hh0.x));
                ll0.y = __float2bfloat16(v1 - __bfloat162float(hh0.y));
                hh1.x = __float2bfloat16(v2); hh1.y = __float2bfloat16(v3);
                ll1.x = __float2bfloat16(v2 - __bfloat162float(hh1.x));
                ll1.y = __float2bfloat16(v3 - __bfloat162float(hh1.y));
                *(__nv_bfloat162*)&Chi[(long)r * N + c]       = hh0;
                *(__nv_bfloat162*)&Clo[(long)r * N + c]       = ll0;
                *(__nv_bfloat162*)&Chi[(long)(r + 8) * N + c] = hh1;
                *(__nv_bfloat162*)&Clo[(long)(r + 8) * N + c] = ll1;
            } else {
                float2 o0; o0.x = v0; o0.y = v1;
                float2 o1; o1.x = v2; o1.y = v3;
                *(float2*)&C[(long)r * N + c]       = o0;
                *(float2*)&C[(long)(r + 8) * N + c] = o1;
            }
        }
#undef LDG
#undef STS
}

// ---------------- score kernel: 64x32 (t,s) tile, 4x2 micro, d-split x4 ----------
// grid (8, 4, 16): z = b*4 + dq. Each block reduces 128 d-values into g_score4[dq].
__global__ __launch_bounds__(256) void score_kernel(
    const float* __restrict__ wq, const float* __restrict__ uh,
    const float* __restrict__ v)
{
    const int b  = blockIdx.z >> 2;
    const int dq = blockIdx.z & 3;
    const int t0 = blockIdx.y * 64;
    const int s0 = blockIdx.x * 32;
    const int dbase = dq * 128;

    __shared__ float wq_s[32][68];   // [d][t], stride 272B (16B aligned)
    __shared__ float uh_s[32][34];   // [d][s], stride 136B (8B aligned)
    __shared__ float v_s[32];

    const int tid = threadIdx.x;
    const int tt  = tid >> 4;        // 0..15 -> t quad (4 rows)
    const int ss  = tid & 15;        // 0..15 -> s pair
    const int lrow = tid >> 2;       // 0..63
    const int lcol = (tid & 3) * 8;  // 0,8,16,24

    const float* wq_b = wq + ((long)b * T_DIM + t0) * D_DIM + dbase;
    const float* uh_b = uh + ((long)b * S_DIM + s0) * D_DIM + dbase;

    float acc[4][2] = {};

    for (int d0 = 0; d0 < 128; d0 += 32) {
        // load wq tile 64t x 32d transposed
        {
            float4 w0 = *(const float4*)&wq_b[(long)lrow * D_DIM + d0 + lcol];
            float4 w1 = *(const float4*)&wq_b[(long)lrow * D_DIM + d0 + lcol + 4];
            wq_s[lcol + 0][lrow] = w0.x; wq_s[lcol + 1][lrow] = w0.y;
            wq_s[lcol + 2][lrow] = w0.z; wq_s[lcol + 3][lrow] = w0.w;
            wq_s[lcol + 4][lrow] = w1.x; wq_s[lcol + 5][lrow] = w1.y;
            wq_s[lcol + 6][lrow] = w1.z; wq_s[lcol + 7][lrow] = w1.w;
        }
        // load uh tile 32s x 32d transposed (first 128 threads)
        if (tid < 128) {
            int srow = tid >> 2;
            float4 u0 = *(const float4*)&uh_b[(long)srow * D_DIM + d0 + lcol];
            float4 u1 = *(const float4*)&uh_b[(long)srow * D_DIM + d0 + lcol + 4];
            uh_s[lcol + 0][srow] = u0.x; uh_s[lcol + 1][srow] = u0.y;
            uh_s[lcol + 2][srow] = u0.z; uh_s[lcol + 3][srow] = u0.w;
            uh_s[lcol + 4][srow] = u1.x; uh_s[lcol + 5][srow] = u1.y;
            uh_s[lcol + 6][srow] = u1.z; uh_s[lcol + 7][srow] = u1.w;
        }
        if (tid < 8) *(float4*)&v_s[tid * 4] = *(const float4*)&v[dbase + d0 + tid * 4];
        __syncthreads();

        #pragma unroll 8
        for (int d = 0; d < 32; d++) {
            float4 a = *(const float4*)&wq_s[d][tt * 4];
            float2 u = *(const float2*)&uh_s[d][ss * 2];
            float vd = v_s[d];
            acc[0][0] = fmaf(vd, tanh_fast(a.x + u.x), acc[0][0]);
            acc[0][1] = fmaf(vd, tanh_fast(a.x + u.y), acc[0][1]);
            acc[1][0] = fmaf(vd, tanh_fast(a.y + u.x), acc[1][0]);
            acc[1][1] = fmaf(vd, tanh_fast(a.y + u.y), acc[1][1]);
            acc[2][0] = fmaf(vd, tanh_fast(a.z + u.x), acc[2][0]);
            acc[2][1] = fmaf(vd, tanh_fast(a.z + u.y), acc[2][1]);
            acc[3][0] = fmaf(vd, tanh_fast(a.w + u.x), acc[3][0]);
            acc[3][1] = fmaf(vd, tanh_fast(a.w + u.y), acc[3][1]);
        }
        __syncthreads();
    }

    float* sp = g_score4[dq];
    #pragma unroll
    for (int i = 0; i < 4; i++) {
        long r = ((long)b * T_DIM + t0 + tt * 4 + i) * S_DIM + s0 + ss * 2;
        float2 o; o.x = acc[i][0]; o.y = acc[i][1];
        *(float2*)&sp[r] = o;
    }
}

// ---------------- masked softmax (sums 4 d-quarters) + fused attn hi/lo split ----
__device__ __forceinline__ void wr_split2(
    __nv_bfloat16* hp, __nv_bfloat16* lp, int c, float a, float b)
{
    __nv_bfloat16 h0 = __float2bfloat16(a);
    __nv_bfloat16 h1 = __float2bfloat16(b);
    __nv_bfloat162 hh; hh.x = h0; hh.y = h1;
    __nv_bfloat162 ll;
    ll.x = __float2bfloat16(a - __bfloat162float(h0));
    ll.y = __float2bfloat16(b - __bfloat162float(h1));
    *(__nv_bfloat162*)(hp + c) = hh;
    *(__nv_bfloat162*)(lp + c) = ll;
}

__global__ __launch_bounds__(256) void softmax_kernel(
    const int* __restrict__ mask,
    __nv_bfloat16* __restrict__ at_hi, __nv_bfloat16* __restrict__ at_lo,
    float* __restrict__ attn_out)
{
    const int lane = threadIdx.x & 31;
    const int w    = threadIdx.x >> 5;
    const int row  = blockIdx.x * 8 + w;    // b*T + t
    const int b    = row >> 8;              // T = 256

    float4 x0, x1;
    {
        const float4* s0 = (const float4*)(g_score4[0] + (long)row * S_DIM);
        const float4* s1 = (const float4*)(g_score4[1] + (long)row * S_DIM);
        const float4* s2 = (const float4*)(g_score4[2] + (long)row * S_DIM);
        const float4* s3 = (const float4*)(g_score4[3] + (long)row * S_DIM);
        float4 a = s0[lane], bq_ = s1[lane], c = s2[lane], d = s3[lane];
        x0.x = (a.x + bq_.x) + (c.x + d.x);
        x0.y = (a.y + bq_.y) + (c.y + d.y);
        x0.z = (a.z + bq_.z) + (c.z + d.z);
        x0.w = (a.w + bq_.w) + (c.w + d.w);
        a = s0[lane + 32]; bq_ = s1[lane + 32]; c = s2[lane + 32]; d = s3[lane + 32];
        x1.x = (a.x + bq_.x) + (c.x + d.x);
        x1.y = (a.y + bq_.y) + (c.y + d.y);
        x1.z = (a.z + bq_.z) + (c.z + d.z);
        x1.w = (a.w + bq_.w) + (c.w + d.w);
    }

    float m = fmaxf(fmaxf(fmaxf(x0.x, x0.y), fmaxf(x0.z, x0.w)),
                    fmaxf(fmaxf(x1.x, x1.y), fmaxf(x1.z, x1.w)));
    #pragma unroll
    for (int o = 16; o > 0; o >>= 1) m = fmaxf(m, __shfl_xor_sync(0xffffffffu, m, o));

    const int4* mp = (const int4*)(mask + b * S_DIM);
    int4 k0 = mp[lane];
    int4 k1 = mp[lane + 32];

    float4 e0, e1;
    e0.x = __expf(x0.x - m) * (1.0f - (float)k0.x);
    e0.y = __expf(x0.y - m) * (1.0f - (float)k0.y);
    e0.z = __expf(x0.z - m) * (1.0f - (float)k0.z);
    e0.w = __expf(x0.w - m) * (1.0f - (float)k0.w);
    e1.x = __expf(x1.x - m) * (1.0f - (float)k1.x);
    e1.y = __expf(x1.y - m) * (1.0f - (float)k1.y);
    e1.z = __expf(x1.z - m) * (1.0f - (float)k1.z);
    e1.w = __expf(x1.w - m) * (1.0f - (float)k1.w);

    float sum = e0.x + e0.y + e0.z + e0.w + e1.x + e1.y + e1.z + e1.w;
    #pragma unroll
    for (int o = 16; o > 0; o >>= 1) sum += __shfl_xor_sync(0xffffffffu, sum, o);

    float inv = 1.0f / sum;
    e0.x *= inv; e0.y *= inv; e0.z *= inv; e0.w *= inv;
    e1.x *= inv; e1.y *= inv; e1.z *= inv; e1.w *= inv;

    __nv_bfloat16* hp = at_hi + (long)row * S_DIM;
    __nv_bfloat16* lp = at_lo + (long)row * S_DIM;
    wr_split2(hp, lp, 4 * lane,       e0.x, e0.y);
    wr_split2(hp, lp, 4 * lane + 2,   e0.z, e0.w);
    wr_split2(hp, lp, 128 + 4 * lane, e1.x, e1.y);
    wr_split2(hp, lp, 130 + 4 * lane, e1.z, e1.w);

    if (attn_out) {
        float4* ao = (float4*)(attn_out + (long)row * S_DIM);
        ao[lane]      = e0;
        ao[lane + 32] = e1;
    }
}

// ---------------- launch ----------------
extern "C" void kernel_launch(void* const* d_in, const int* in_sizes, int n_in,
                              void* d_out, int out_size)
{
    const float* output  = (const float*)d_in[0];
    const float* context = (const float*)d_in[1];
    const int*   mask    = (const int*)d_in[2];
    const float* Wq      = (const float*)d_in[3];
    const float* bq      = (const float*)d_in[4];
    const float* Wc      = (const float*)d_in[5];
    const float* v       = (const float*)d_in[6];
    const float* Wout    = (const float*)d_in[7];
    const float* bout    = (const float*)d_in[8];

    float *wq, *uh, *out2;
    cudaGetSymbolAddress((void**)&wq,   g_wq);
    cudaGetSymbolAddress((void**)&uh,   g_uh);
    cudaGetSymbolAddress((void**)&out2, g_out2);

    __nv_bfloat16 *out_hi, *out_lo, *ctx_hi, *ctx_lo, *ctxT_hi, *ctxT_lo;
    __nv_bfloat16 *WqT_hi, *WqT_lo, *WcT_hi, *WcT_lo, *WoT_hi, *WoT_lo;
    __nv_bfloat16 *at_hi, *at_lo, *mx_hi, *mx_lo;
    cudaGetSymbolAddress((void**)&out_hi,  g_out_hi);
    cudaGetSymbolAddress((void**)&out_lo,  g_out_lo);
    cudaGetSymbolAddress((void**)&ctx_hi,  g_ctx_hi);
    cudaGetSymbolAddress((void**)&ctx_lo,  g_ctx_lo);
    cudaGetSymbolAddress((void**)&ctxT_hi, g_ctxT_hi);
    cudaGetSymbolAddress((void**)&ctxT_lo, g_ctxT_lo);
    cudaGetSymbolAddress((void**)&WqT_hi,  g_WqT_hi);
    cudaGetSymbolAddress((void**)&WqT_lo,  g_WqT_lo);
    cudaGetSymbolAddress((void**)&WcT_hi,  g_WcT_hi);
    cudaGetSymbolAddress((void**)&WcT_lo,  g_WcT_lo);
    cudaGetSymbolAddress((void**)&WoT_hi,  g_WoT_hi);
    cudaGetSymbolAddress((void**)&WoT_lo,  g_WoT_lo);
    cudaGetSymbolAddress((void**)&at_hi,   g_at_hi);
    cudaGetSymbolAddress((void**)&at_lo,   g_at_lo);
    cudaGetSymbolAddress((void**)&mx_hi,   g_mx_hi);
    cudaGetSymbolAddress((void**)&mx_lo,   g_mx_lo);

    float* out = (float*)d_out;
    const int out_elems  = B_DIM * T_DIM * D_DIM;   // 524288
    const int attn_elems = B_DIM * T_DIM * S_DIM;   // 262144
    float* attn_out = (out_size >= out_elems + attn_elems) ? (out + out_elems) : nullptr;

    const long sCtxT = (long)S_DIM * D_DIM;

    // 1) all staging in one wide launch
    stage_all<<<2560, 256>>>(output, context, Wq, Wc, Wout);

    // 2) fork: wq GEMM on s0; uh GEMM then out2 GEMM on s1
    cudaEventRecord(evFork, 0);
    cudaStreamWaitEvent(s1, evFork, 0);

    gemm_bf16s<<<dim3(8, 16, 1), 256>>>(out_hi, out_lo, WqT_hi, WqT_lo, 512,
                                        wq, nullptr, nullptr, nullptr,
                                        512, 512, bq, 0, 0, 0);
    gemm_bf16s<<<dim3(8, 16, 1), 256, 0, s1>>>(ctx_hi, ctx_lo, WcT_hi, WcT_lo, 512,
                                               uh, nullptr, nullptr, nullptr,
                                               512, 512, nullptr, 0, 0, 0);
    cudaEventRecord(ev1, s1);
    // out2 = output @ Wout[512:1024] — off critical path, overlaps score
    gemm_bf16s<<<dim3(8, 16, 1), 256, 0, s1>>>(out_hi, out_lo,
                                               WoT_hi + 512, WoT_lo + 512, 1024,
                                               out2, nullptr, nullptr, nullptr,
                                               512, 512, nullptr, 0, 0, 0);
    cudaEventRecord(ev2, s1);

    // 3) score (needs wq + uh) -> softmax -> mix -> final
    cudaStreamWaitEvent(0, ev1, 0);
    score_kernel<<<dim3(8, 4, 16), 256>>>(wq, uh, v);
    softmax_kernel<<<128, 256>>>(mask, at_hi, at_lo, attn_out);
    gemm_bf16s<<<dim3(8, 4, 4), 256>>>(at_hi, at_lo, ctxT_hi, ctxT_lo, 256,
                                       nullptr, mx_hi, mx_lo, nullptr,
                                       512, 256, nullptr,
                                       (long)T_DIM * S_DIM, sCtxT, (long)T_DIM * D_DIM);
    cudaStreamWaitEvent(0, ev2, 0);
    gemm_bf16s<<<dim3(8, 16, 1), 256>>>(mx_hi, mx_lo, WoT_hi, WoT_lo, 1024,
                                        out, nullptr, nullptr, out2,
                                        512, 512, bout, 0, 0, 0);
}

// round 17
// speedup vs baseline: 1.2904x; 1.2904x over previous
#include <cuda_runtime.h>
#include <cuda_bf16.h>
#include <cstdint>

#define B_DIM 4
#define T_DIM 256
#define S_DIM 256
#define D_DIM 512

// ---------------- fp32 scratch ----------------
__device__ float g_wq[B_DIM * T_DIM * D_DIM];        // 2 MB
__device__ float g_uh[B_DIM * S_DIM * D_DIM];        // 2 MB
__device__ float g_score2[2][B_DIM * T_DIM * S_DIM]; // 2 MB (two d-halves)

// ---------------- bf16 split scratch ----------------
__device__ __nv_bfloat16 g_out_hi[524288],  g_out_lo[524288];    // output [1024,512]
__device__ __nv_bfloat16 g_ctx_hi[524288],  g_ctx_lo[524288];    // context [1024,512]
__device__ __nv_bfloat16 g_ctxT_hi[524288], g_ctxT_lo[524288];   // context^T [4][512][256]
__device__ __nv_bfloat16 g_WqT_hi[262144],  g_WqT_lo[262144];    // Wq^T [512,512]
__device__ __nv_bfloat16 g_WcT_hi[262144],  g_WcT_lo[262144];    // Wc^T [512,512]
__device__ __nv_bfloat16 g_WoT_hi[524288],  g_WoT_lo[524288];    // Wout^T [512,1024]
__device__ __nv_bfloat16 g_at_hi[262144],   g_at_lo[262144];     // attn [1024,256]
__device__ __nv_bfloat16 g_mx_hi[524288],   g_mx_lo[524288];     // mix [1024,512]

// ---------------- streams/events for graph fork-join (created before main) ----------
static cudaStream_t s1;
static cudaEvent_t  evFork, ev1;
struct StreamInit {
    StreamInit() {
        cudaStreamCreateWithFlags(&s1, cudaStreamNonBlocking);
        cudaEventCreateWithFlags(&evFork, cudaEventDisableTiming);
        cudaEventCreateWithFlags(&ev1, cudaEventDisableTiming);
    }
};
static StreamInit g_streams_init;

__device__ __forceinline__ float tanh_fast(float x) {
    float y;
    asm("tanh.approx.f32 %0, %1;" : "=f"(y) : "f"(x));
    return y;
}

// ---------------- fused staging: all splits + transposes in ONE launch ------------
__device__ __forceinline__ void do_split_block(
    const float* __restrict__ src,
    __nv_bfloat16* __restrict__ hi, __nv_bfloat16* __restrict__ lo, int blk)
{
    int i = blk * 1024 + threadIdx.x * 4;
    float4 x = *(const float4*)(src + i);
    __nv_bfloat16 h0 = __float2bfloat16(x.x);
    __nv_bfloat16 h1 = __float2bfloat16(x.y);
    __nv_bfloat16 h2 = __float2bfloat16(x.z);
    __nv_bfloat16 h3 = __float2bfloat16(x.w);
    __nv_bfloat162 hh0; hh0.x = h0; hh0.y = h1;
    __nv_bfloat162 hh1; hh1.x = h2; hh1.y = h3;
    __nv_bfloat162 ll0;
    ll0.x = __float2bfloat16(x.x - __bfloat162float(h0));
    ll0.y = __float2bfloat16(x.y - __bfloat162float(h1));
    __nv_bfloat162 ll1;
    ll1.x = __float2bfloat16(x.z - __bfloat162float(h2));
    ll1.y = __float2bfloat16(x.w - __bfloat162float(h3));
    *(__nv_bfloat162*)(hi + i)     = hh0;
    *(__nv_bfloat162*)(hi + i + 2) = hh1;
    *(__nv_bfloat162*)(lo + i)     = ll0;
    *(__nv_bfloat162*)(lo + i + 2) = ll1;
}

__device__ __forceinline__ void do_splitT_block(
    float (*tile)[33],
    const float* __restrict__ src,
    __nv_bfloat16* __restrict__ hiT, __nv_bfloat16* __restrict__ loT,
    int R, int C, int bx, int by)
{
    const int r0 = by * 32, c0 = bx * 32;
    const int tx = threadIdx.x & 31, ty = threadIdx.x >> 5;   // 32 x 8

    #pragma unroll
    for (int i = 0; i < 4; i++)
        tile[ty + i * 8][tx] = src[(long)(r0 + ty + i * 8) * C + c0 + tx];
    __syncthreads();
    #pragma unroll
    for (int i = 0; i < 4; i++) {
        int cr = c0 + ty + i * 8;
        float x = tile[tx][ty + i * 8];
        __nv_bfloat16 h = __float2bfloat16(x);
        hiT[(long)cr * R + r0 + tx] = h;
        loT[(long)cr * R + r0 + tx] = __float2bfloat16(x - __bfloat162float(h));
    }
}

__global__ __launch_bounds__(256) void stage_all(
    const float* __restrict__ output, const float* __restrict__ context,
    const float* __restrict__ Wq, const float* __restrict__ Wc,
    const float* __restrict__ Wout)
{
    __shared__ float tile[32][33];
    const int j = blockIdx.x;
    if (j < 512) {
        do_split_block(output, g_out_hi, g_out_lo, j);
    } else if (j < 1024) {
        do_split_block(context, g_ctx_hi, g_ctx_lo, j - 512);
    } else if (j < 1280) {
        int k = j - 1024;
        do_splitT_block(tile, Wq, g_WqT_hi, g_WqT_lo, 512, 512, k & 15, k >> 4);
    } else if (j < 1536) {
        int k = j - 1280;
        do_splitT_block(tile, Wc, g_WcT_hi, g_WcT_lo, 512, 512, k & 15, k >> 4);
    } else if (j < 2048) {
        int k = j - 1536;
        do_splitT_block(tile, Wout, g_WoT_hi, g_WoT_lo, 1024, 512, k & 15, k >> 4);
    } else {
        int k = j - 2048;
        int z = k >> 7, rem = k & 127;
        const long s = (long)S_DIM * D_DIM;
        do_splitT_block(tile, context + z * s, g_ctxT_hi + z * s, g_ctxT_lo + z * s,
                        256, 512, rem & 15, rem >> 4);
    }
}

// ---------------- split-bf16 tensor-core GEMM (32x64 tile, 256 thr, 8 warps) ----
// Smaller tile -> 2x the CTAs -> ~2 CTAs/SM hides MMA/LDS latency.
// C[M,N] = [A|A2][M,Ktot] @ BT[N][Ktot] (+bias). Warp tile 16x16.
#define MMA_BF16(d, a, b)                                                     \
    asm volatile("mma.sync.aligned.m16n8k16.row.col.f32.bf16.bf16.f32 "       \
                 "{%0,%1,%2,%3},{%4,%5,%6,%7},{%8,%9},{%0,%1,%2,%3};"         \
                 : "+f"((d)[0]), "+f"((d)[1]), "+f"((d)[2]), "+f"((d)[3])     \
                 : "r"((a)[0]), "r"((a)[1]), "r"((a)[2]), "r"((a)[3]),        \
                   "r"((b)[0]), "r"((b)[1]))

__global__ __launch_bounds__(256, 2) void gemm_bf16s(
    const __nv_bfloat16* __restrict__ Ahi, const __nv_bfloat16* __restrict__ Alo,
    const __nv_bfloat16* __restrict__ A2hi, const __nv_bfloat16* __restrict__ A2lo,
    const __nv_bfloat16* __restrict__ BThi, const __nv_bfloat16* __restrict__ BTlo,
    float* __restrict__ C,
    __nv_bfloat16* __restrict__ Chi, __nv_bfloat16* __restrict__ Clo,
    int N, int Ka, int Ktot, const float* __restrict__ bias,
    long sA, long sB, long sC)
{
    Ahi  += (long)blockIdx.z * sA;  Alo  += (long)blockIdx.z * sA;
    BThi += (long)blockIdx.z * sB;  BTlo += (long)blockIdx.z * sB;
    if (C)   C   += (long)blockIdx.z * sC;
    if (Chi) { Chi += (long)blockIdx.z * sC; Clo += (long)blockIdx.z * sC; }

    __shared__ __align__(16) __nv_bfloat16 As[2][2][32 * 24];
    __shared__ __align__(16) __nv_bfloat16 Bs[2][2][64 * 24];

    const int tid  = threadIdx.x;
    const int lane = tid & 31;
    const int wid  = tid >> 5;
    const int wm   = wid & 1;           // 2 m-slots of 16
    const int wn   = wid >> 1;          // 4 n-slots of 16
    const int m0   = blockIdx.y * 32;
    const int n0   = blockIdx.x * 64;
    const int g    = lane >> 2;
    const int t    = lane & 3;
    const int row4 = tid >> 2;          // 0..63
    const int part = (tid >> 1) & 1;
    const int seg  = tid & 1;

    const int Kb = Ktot - Ka;
    const int KT = Ktot >> 4;

    int4 ra, rb;

#define LDG(kt) {                                                              \
        int gk = (kt) << 4;                                                    \
        long boff = (long)(n0 + row4) * Ktot + gk + seg * 8;                   \
        rb = *(const int4*)((part ? BTlo : BThi) + boff);                      \
        if (tid < 128) {                                                       \
            const __nv_bfloat16* ap;                                           \
            if (A2hi && gk >= Ka)                                              \
                ap = (part ? A2lo : A2hi) + (long)(m0 + row4) * Kb + (gk - Ka) + seg * 8; \
            else                                                               \
                ap = (part ? Alo : Ahi) + (long)(m0 + row4) * Ka + gk + seg * 8; \
            ra = *(const int4*)ap;                                             \
        }                                                                      \
    }

#define STS(bf) {                                                              \
        int so = row4 * 24 + seg * 8;                                          \
        *(int4*)&Bs[bf][part][so] = rb;                                        \
        if (tid < 128) *(int4*)&As[bf][part][so] = ra;                         \
    }

    float acc[2][4] = {};

    LDG(0); STS(0);
    __syncthreads();

    for (int kt = 0; kt < KT; kt++) {
        const int buf = kt & 1;
        if (kt + 1 < KT) LDG(kt + 1);

        uint32_t ah[4], al[4], bh[2][2], bl[2][2];
        const __nv_bfloat16* pah = &As[buf][0][0];
        const __nv_bfloat16* pal = &As[buf][1][0];
        const __nv_bfloat16* pbh = &Bs[buf][0][0];
        const __nv_bfloat16* pbl = &Bs[buf][1][0];

        {
            int base = (wm * 16 + g) * 24 + 2 * t;
            ah[0] = *(const uint32_t*)(pah + base);
            ah[1] = *(const uint32_t*)(pah + base + 8 * 24);
            ah[2] = *(const uint32_t*)(pah + base + 8);
            ah[3] = *(const uint32_t*)(pah + base + 8 * 24 + 8);
            al[0] = *(const uint32_t*)(pal + base);
            al[1] = *(const uint32_t*)(pal + base + 8 * 24);
            al[2] = *(const uint32_t*)(pal + base + 8);
            al[3] = *(const uint32_t*)(pal + base + 8 * 24 + 8);
        }
        #pragma unroll
        for (int nj = 0; nj < 2; nj++) {
            int base = (wn * 16 + nj * 8 + g) * 24 + 2 * t;
            bh[nj][0] = *(const uint32_t*)(pbh + base);
            bh[nj][1] = *(const uint32_t*)(pbh + base + 8);
            bl[nj][0] = *(const uint32_t*)(pbl + base);
            bl[nj][1] = *(const uint32_t*)(pbl + base + 8);
        }

        #pragma unroll
        for (int nj = 0; nj < 2; nj++) {
            MMA_BF16(acc[nj], ah, bh[nj]);
            MMA_BF16(acc[nj], ah, bl[nj]);
            MMA_BF16(acc[nj], al, bh[nj]);
        }

        if (kt + 1 < KT) STS(buf ^ 1);
        __syncthreads();
    }

    #pragma unroll
    for (int nj = 0; nj < 2; nj++) {
        int r = m0 + wm * 16 + g;
        int c = n0 + wn * 16 + nj * 8 + 2 * t;
        float b0 = 0.f, b1 = 0.f;
        if (bias) { b0 = bias[c]; b1 = bias[c + 1]; }
        float v0 = acc[nj][0] + b0, v1 = acc[nj][1] + b1;
        float v2 = acc[nj][2] + b0, v3 = acc[nj][3] + b1;
        if (Chi) {
            __nv_bfloat162 hh0, ll0, hh1, ll1;
            hh0.x = __float2bfloat16(v0); hh0.y = __float2bfloat16(v1);
            ll0.x = __float2bfloat16(v0 - __bfloat162float(hh0.x));
            ll0.y = __float2bfloat16(v1 - __bfloat162float(hh0.y));
            hh1.x = __float2bfloat16(v2); hh1.y = __float2bfloat16(v3);
            ll1.x = __float2bfloat16(v2 - __bfloat162float(hh1.x));
            ll1.y = __float2bfloat16(v3 - __bfloat162float(hh1.y));
            *(__nv_bfloat162*)&Chi[(long)r * N + c]       = hh0;
            *(__nv_bfloat162*)&Clo[(long)r * N + c]       = ll0;
            *(__nv_bfloat162*)&Chi[(long)(r + 8) * N + c] = hh1;
            *(__nv_bfloat162*)&Clo[(long)(r + 8) * N + c] = ll1;
        } else {
            float2 o0; o0.x = v0; o0.y = v1;
            float2 o1; o1.x = v2; o1.y = v3;
            *(float2*)&C[(long)r * N + c]       = o0;
            *(float2*)&C[(long)(r + 8) * N + c] = o1;
        }
    }
#undef LDG
#undef STS
}

// ---------------- score kernel: d-split x2 (round-13 proven) ----------------
__global__ __launch_bounds__(256) void score_kernel(
    const float* __restrict__ wq, const float* __restrict__ uh,
    const float* __restrict__ v)
{
    const int b     = blockIdx.z >> 1;
    const int dhalf = blockIdx.z & 1;
    const int t0 = blockIdx.y * 32;
    const int s0 = blockIdx.x * 32;
    const int dbase = dhalf * 256;

    __shared__ float wq_s[64][34];
    __shared__ float uh_s[64][34];
    __shared__ float v_s[64];

    const int tid  = threadIdx.x;
    const int tt   = tid >> 4;
    const int ss   = tid & 15;
    const int lrow = tid >> 3;
    const int lcol = (tid & 7) * 8;

    const float* wq_b = wq + ((long)b * T_DIM + t0) * D_DIM + dbase;
    const float* uh_b = uh + ((long)b * S_DIM + s0) * D_DIM + dbase;

    float acc00 = 0.f, acc01 = 0.f, acc10 = 0.f, acc11 = 0.f;

    for (int d0 = 0; d0 < 256; d0 += 64) {
        float4 w0 = *(const float4*)&wq_b[(long)lrow * D_DIM + d0 + lcol];
        float4 w1 = *(const float4*)&wq_b[(long)lrow * D_DIM + d0 + lcol + 4];
        float4 u0 = *(const float4*)&uh_b[(long)lrow * D_DIM + d0 + lcol];
        float4 u1 = *(const float4*)&uh_b[(long)lrow * D_DIM + d0 + lcol + 4];

        wq_s[lcol + 0][lrow] = w0.x; wq_s[lcol + 1][lrow] = w0.y;
        wq_s[lcol + 2][lrow] = w0.z; wq_s[lcol + 3][lrow] = w0.w;
        wq_s[lcol + 4][lrow] = w1.x; wq_s[lcol + 5][lrow] = w1.y;
        wq_s[lcol + 6][lrow] = w1.z; wq_s[lcol + 7][lrow] = w1.w;
        uh_s[lcol + 0][lrow] = u0.x; uh_s[lcol + 1][lrow] = u0.y;
        uh_s[lcol + 2][lrow] = u0.z; uh_s[lcol + 3][lrow] = u0.w;
        uh_s[lcol + 4][lrow] = u1.x; uh_s[lcol + 5][lrow] = u1.y;
        uh_s[lcol + 6][lrow] = u1.z; uh_s[lcol + 7][lrow] = u1.w;
        if (tid < 16) *(float4*)&v_s[tid * 4] = *(const float4*)&v[dbase + d0 + tid * 4];
        __syncthreads();

        #pragma unroll 16
        for (int d = 0; d < 64; d++) {
            float2 a = *(const float2*)&wq_s[d][tt * 2];
            float2 u = *(const float2*)&uh_s[d][ss * 2];
            float vd = v_s[d];
            acc00 = fmaf(vd, tanh_fast(a.x + u.x), acc00);
            acc01 = fmaf(vd, tanh_fast(a.x + u.y), acc01);
            acc10 = fmaf(vd, tanh_fast(a.y + u.x), acc10);
            acc11 = fmaf(vd, tanh_fast(a.y + u.y), acc11);
        }
        __syncthreads();
    }

    float* sp = g_score2[dhalf];
    long base = ((long)b * T_DIM + t0 + tt * 2) * S_DIM + s0 + ss * 2;
    sp[base]             = acc00;
    sp[base + 1]         = acc01;
    sp[base + S_DIM]     = acc10;
    sp[base + S_DIM + 1] = acc11;
}

// ---------------- masked softmax (sums d-halves) + fused attn hi/lo split --------
__device__ __forceinline__ void wr_split2(
    __nv_bfloat16* hp, __nv_bfloat16* lp, int c, float a, float b)
{
    __nv_bfloat16 h0 = __float2bfloat16(a);
    __nv_bfloat16 h1 = __float2bfloat16(b);
    __nv_bfloat162 hh; hh.x = h0; hh.y = h1;
    __nv_bfloat162 ll;
    ll.x = __float2bfloat16(a - __bfloat162float(h0));
    ll.y = __float2bfloat16(b - __bfloat162float(h1));
    *(__nv_bfloat162*)(hp + c) = hh;
    *(__nv_bfloat162*)(lp + c) = ll;
}

__global__ __launch_bounds__(256) void softmax_kernel(
    const int* __restrict__ mask,
    __nv_bfloat16* __restrict__ at_hi, __nv_bfloat16* __restrict__ at_lo,
    float* __restrict__ attn_out)
{
    const int lane = threadIdx.x & 31;
    const int w    = threadIdx.x >> 5;
    const int row  = blockIdx.x * 8 + w;    // b*T + t
    const int b    = row >> 8;              // T = 256

    const float4* sr0 = (const float4*)(g_score2[0] + (long)row * S_DIM);
    const float4* sr1 = (const float4*)(g_score2[1] + (long)row * S_DIM);
    float4 p0 = sr0[lane], q0 = sr1[lane];
    float4 p1 = sr0[lane + 32], q1 = sr1[lane + 32];
    float4 x0, x1;
    x0.x = p0.x + q0.x; x0.y = p0.y + q0.y; x0.z = p0.z + q0.z; x0.w = p0.w + q0.w;
    x1.x = p1.x + q1.x; x1.y = p1.y + q1.y; x1.z = p1.z + q1.z; x1.w = p1.w + q1.w;

    float m = fmaxf(fmaxf(fmaxf(x0.x, x0.y), fmaxf(x0.z, x0.w)),
                    fmaxf(fmaxf(x1.x, x1.y), fmaxf(x1.z, x1.w)));
    #pragma unroll
    for (int o = 16; o > 0; o >>= 1) m = fmaxf(m, __shfl_xor_sync(0xffffffffu, m, o));

    const int4* mp = (const int4*)(mask + b * S_DIM);
    int4 k0 = mp[lane];
    int4 k1 = mp[lane + 32];

    float4 e0, e1;
    e0.x = __expf(x0.x - m) * (1.0f - (float)k0.x);
    e0.y = __expf(x0.y - m) * (1.0f - (float)k0.y);
    e0.z = __expf(x0.z - m) * (1.0f - (float)k0.z);
    e0.w = __expf(x0.w - m) * (1.0f - (float)k0.w);
    e1.x = __expf(x1.x - m) * (1.0f - (float)k1.x);
    e1.y = __expf(x1.y - m) * (1.0f - (float)k1.y);
    e1.z = __expf(x1.z - m) * (1.0f - (float)k1.z);
    e1.w = __expf(x1.w - m) * (1.0f - (float)k1.w);

    float sum = e0.x + e0.y + e0.z + e0.w + e1.x + e1.y + e1.z + e1.w;
    #pragma unroll
    for (int o = 16; o > 0; o >>= 1) sum += __shfl_xor_sync(0xffffffffu, sum, o);

    float inv = 1.0f / sum;
    e0.x *= inv; e0.y *= inv; e0.z *= inv; e0.w *= inv;
    e1.x *= inv; e1.y *= inv; e1.z *= inv; e1.w *= inv;

    __nv_bfloat16* hp = at_hi + (long)row * S_DIM;
    __nv_bfloat16* lp = at_lo + (long)row * S_DIM;
    wr_split2(hp, lp, 4 * lane,       e0.x, e0.y);
    wr_split2(hp, lp, 4 * lane + 2,   e0.z, e0.w);
    wr_split2(hp, lp, 128 + 4 * lane, e1.x, e1.y);
    wr_split2(hp, lp, 130 + 4 * lane, e1.z, e1.w);

    if (attn_out) {
        float4* ao = (float4*)(attn_out + (long)row * S_DIM);
        ao[lane]      = e0;
        ao[lane + 32] = e1;
    }
}

// ---------------- launch ----------------
extern "C" void kernel_launch(void* const* d_in, const int* in_sizes, int n_in,
                              void* d_out, int out_size)
{
    const float* output  = (const float*)d_in[0];
    const float* context = (const float*)d_in[1];
    const int*   mask    = (const int*)d_in[2];
    const float* Wq      = (const float*)d_in[3];
    const float* bq      = (const float*)d_in[4];
    const float* Wc      = (const float*)d_in[5];
    const float* v       = (const float*)d_in[6];
    const float* Wout    = (const float*)d_in[7];
    const float* bout    = (const float*)d_in[8];

    float *wq, *uh;
    cudaGetSymbolAddress((void**)&wq, g_wq);
    cudaGetSymbolAddress((void**)&uh, g_uh);

    __nv_bfloat16 *out_hi, *out_lo, *ctx_hi, *ctx_lo, *ctxT_hi, *ctxT_lo;
    __nv_bfloat16 *WqT_hi, *WqT_lo, *WcT_hi, *WcT_lo, *WoT_hi, *WoT_lo;
    __nv_bfloat16 *at_hi, *at_lo, *mx_hi, *mx_lo;
    cudaGetSymbolAddress((void**)&out_hi,  g_out_hi);
    cudaGetSymbolAddress((void**)&out_lo,  g_out_lo);
    cudaGetSymbolAddress((void**)&ctx_hi,  g_ctx_hi);
    cudaGetSymbolAddress((void**)&ctx_lo,  g_ctx_lo);
    cudaGetSymbolAddress((void**)&ctxT_hi, g_ctxT_hi);
    cudaGetSymbolAddress((void**)&ctxT_lo, g_ctxT_lo);
    cudaGetSymbolAddress((void**)&WqT_hi,  g_WqT_hi);
    cudaGetSymbolAddress((void**)&WqT_lo,  g_WqT_lo);
    cudaGetSymbolAddress((void**)&WcT_hi,  g_WcT_hi);
    cudaGetSymbolAddress((void**)&WcT_lo,  g_WcT_lo);
    cudaGetSymbolAddress((void**)&WoT_hi,  g_WoT_hi);
    cudaGetSymbolAddress((void**)&WoT_lo,  g_WoT_lo);
    cudaGetSymbolAddress((void**)&at_hi,   g_at_hi);
    cudaGetSymbolAddress((void**)&at_lo,   g_at_lo);
    cudaGetSymbolAddress((void**)&mx_hi,   g_mx_hi);
    cudaGetSymbolAddress((void**)&mx_lo,   g_mx_lo);

    float* out = (float*)d_out;
    const int out_elems  = B_DIM * T_DIM * D_DIM;   // 524288
    const int attn_elems = B_DIM * T_DIM * S_DIM;   // 262144
    float* attn_out = (out_size >= out_elems + attn_elems) ? (out + out_elems) : nullptr;

    const long sCtxT = (long)S_DIM * D_DIM;

    // 1) all staging in one wide launch
    stage_all<<<2560, 256>>>(output, context, Wq, Wc, Wout);

    // 2) wq GEMM (s0) and uh GEMM (s1) concurrently
    cudaEventRecord(evFork, 0);
    cudaStreamWaitEvent(s1, evFork, 0);

    gemm_bf16s<<<dim3(8, 32, 1), 256>>>(out_hi, out_lo, nullptr, nullptr,
                                        WqT_hi, WqT_lo, wq, nullptr, nullptr,
                                        512, 512, 512, bq, 0, 0, 0);
    gemm_bf16s<<<dim3(8, 32, 1), 256, 0, s1>>>(ctx_hi, ctx_lo, nullptr, nullptr,
                                               WcT_hi, WcT_lo, uh, nullptr, nullptr,
                                               512, 512, 512, nullptr, 0, 0, 0);
    cudaEventRecord(ev1, s1);
    cudaStreamWaitEvent(0, ev1, 0);

    // 3) score (d-split x2) -> softmax -> mix GEMM -> final GEMM (K=1024 concat)
    score_kernel<<<dim3(8, 8, 8), 256>>>(wq, uh, v);
    softmax_kernel<<<128, 256>>>(mask, at_hi, at_lo, attn_out);
    gemm_bf16s<<<dim3(8, 8, 4), 256>>>(at_hi, at_lo, nullptr, nullptr,
                                       ctxT_hi, ctxT_lo, nullptr, mx_hi, mx_lo,
                                       512, 256, 256, nullptr,
                                       (long)T_DIM * S_DIM, sCtxT, (long)T_DIM * D_DIM);
    gemm_bf16s<<<dim3(8, 32, 1), 256>>>(mx_hi, mx_lo, out_hi, out_lo,
                                        WoT_hi, WoT_lo, out, nullptr, nullptr,
                                        512, 512, 1024, bout, 0, 0, 0);
}